// round 16
// baseline (speedup 1.0000x reference)
#include <cuda_runtime.h>
#include <cuda_fp16.h>
#include <mma.h>
#include <math.h>
#include <stdint.h>

using namespace nvcuda;

// ---------------- problem constants ----------------
#define TT 8192
#define DD 1024
#define EE 8
#define HH 3072
#define PP (TT * 2)

// ---------------- scratch (device globals; ~267 MB) ----------------
__device__ int    g_counts[EE];
__device__ int    g_cursor[EE];
__device__ int    g_offsets[EE + 1];
__device__ int    g_tok[PP];
__device__ float  g_wgt[PP];
__device__ int    g_te[TT * 2];
__device__ float  g_tw[TT * 2];
__device__ __half g_xh[(size_t)TT * DD];
__device__ __half g_w1h[(size_t)EE * DD * HH];
__device__ __half g_w3h[(size_t)EE * DD * HH];
__device__ __half g_w2h[(size_t)EE * HH * DD];
__device__ __half g_h[(size_t)PP * HH];

__device__ __forceinline__ float silu_f(float a) { return a / (1.f + __expf(-a)); }

__device__ __forceinline__ uint4 f8h8(float4 a, float4 b) {
    __half2 h0 = __floats2half2_rn(a.x, a.y);
    __half2 h1 = __floats2half2_rn(a.z, a.w);
    __half2 h2 = __floats2half2_rn(b.x, b.y);
    __half2 h3 = __floats2half2_rn(b.z, b.w);
    uint4 u;
    u.x = *(uint32_t*)&h0; u.y = *(uint32_t*)&h1;
    u.z = *(uint32_t*)&h2; u.w = *(uint32_t*)&h3;
    return u;
}
__device__ __forceinline__ uint32_t smem_u32(const void* p) {
    uint32_t a;
    asm("{ .reg .u64 t; cvta.to.shared.u64 t, %1; cvt.u32.u64 %0, t; }" : "=r"(a) : "l"(p));
    return a;
}
__device__ __forceinline__ void cp16(uint32_t dst, const void* src, uint32_t nbytes) {
    asm volatile("cp.async.cg.shared.global [%0], [%1], 16, %2;"
                 :: "r"(dst), "l"(src), "r"(nbytes));
}
__device__ __forceinline__ void cp_commit() { asm volatile("cp.async.commit_group;"); }
template <int N>
__device__ __forceinline__ void cp_wait() { asm volatile("cp.async.wait_group %0;" :: "n"(N)); }

// ---------------- init ----------------
__global__ void k_init(float* __restrict__ out) {
    int i = blockIdx.x * blockDim.x + threadIdx.x;
    if (i < EE) { g_counts[i] = 0; g_cursor[i] = 0; }
    int stride = gridDim.x * blockDim.x;
    for (int j = i; j < TT * DD; j += stride) out[j] = 0.f;
}

// ---- conversions: device globals referenced DIRECTLY (never as host-side args) ----
__global__ void k_xtoh(const float* __restrict__ in) {
    size_t i = ((size_t)blockIdx.x * blockDim.x + threadIdx.x) * 8;
    float4 a = *(const float4*)(in + i);
    float4 b = *(const float4*)(in + i + 4);
    *(uint4*)(g_xh + i) = f8h8(a, b);
}
__global__ void k_w1toh(const float* __restrict__ in) {
    size_t i = ((size_t)blockIdx.x * blockDim.x + threadIdx.x) * 8;
    float4 a = *(const float4*)(in + i);
    float4 b = *(const float4*)(in + i + 4);
    *(uint4*)(g_w1h + i) = f8h8(a, b);
}
__global__ void k_w3toh(const float* __restrict__ in) {
    size_t i = ((size_t)blockIdx.x * blockDim.x + threadIdx.x) * 8;
    float4 a = *(const float4*)(in + i);
    float4 b = *(const float4*)(in + i + 4);
    *(uint4*)(g_w3h + i) = f8h8(a, b);
}
__global__ void k_w2toh(const float* __restrict__ in) {
    size_t i = ((size_t)blockIdx.x * blockDim.x + threadIdx.x) * 8;
    float4 a = *(const float4*)(in + i);
    float4 b = *(const float4*)(in + i + 4);
    *(uint4*)(g_w2h + i) = f8h8(a, b);
}

// ---------------- gating (R13 form) ----------------
__global__ void k_gate(const float* __restrict__ x, const float* __restrict__ gw) {
    int gid = blockIdx.x * blockDim.x + threadIdx.x;
    int t = gid >> 5, lane = gid & 31;
    if (t >= TT) return;
    const float* xr = x + (size_t)t * DD;
    float acc[EE];
#pragma unroll
    for (int e = 0; e < EE; e++) acc[e] = 0.f;
    for (int d = lane; d < DD; d += 32) {
        float xv = xr[d];
        const float4* g4 = (const float4*)(gw + (size_t)d * EE);
        float4 a = g4[0], b = g4[1];
        acc[0] += xv * a.x; acc[1] += xv * a.y; acc[2] += xv * a.z; acc[3] += xv * a.w;
        acc[4] += xv * b.x; acc[5] += xv * b.y; acc[6] += xv * b.z; acc[7] += xv * b.w;
    }
#pragma unroll
    for (int e = 0; e < EE; e++)
#pragma unroll
        for (int o = 16; o; o >>= 1) acc[e] += __shfl_xor_sync(0xffffffffu, acc[e], o);
    if (lane == 0) {
        int e0 = 0;
#pragma unroll
        for (int e = 1; e < EE; e++) if (acc[e] > acc[e0]) e0 = e;
        int e1 = (e0 == 0) ? 1 : 0;
#pragma unroll
        for (int e = 0; e < EE; e++) if (e != e0 && acc[e] > acc[e1]) e1 = e;
        float w0 = 1.f / (1.f + expf(acc[e1] - acc[e0]));
        g_te[2 * t] = e0; g_te[2 * t + 1] = e1;
        g_tw[2 * t] = w0; g_tw[2 * t + 1] = 1.f - w0;
        atomicAdd(&g_counts[e0], 1);
        atomicAdd(&g_counts[e1], 1);
    }
}

__global__ void k_scan() {
    int s = 0;
    g_offsets[0] = 0;
    for (int e = 0; e < EE; e++) { s += g_counts[e]; g_offsets[e + 1] = s; }
}

__global__ void k_scatter() {
    int t = blockIdx.x * blockDim.x + threadIdx.x;
    if (t >= TT) return;
#pragma unroll
    for (int k = 0; k < 2; k++) {
        int e = g_te[2 * t + k];
        int pos = g_offsets[e] + atomicAdd(&g_cursor[e], 1);
        g_tok[pos] = t;
        g_wgt[pos] = g_tw[2 * t + k];
    }
}

// ============================================================================
// GEMM1: h = wgt * silu(x@w1) * (x@w3) — wmma, 128M x 64N x 32K (R13 tile)
// 4-stage cp.async pipeline; next-stage loads issued BEFORE compute.
// stage 19456B: sA(128x40h) @0, sB1(32x72h) @10240, sB3 @14848
// ============================================================================
#define STG1 19456
#define SM1_BYTES (4 * STG1)   // 77824

__global__ void __launch_bounds__(256) k_gemm1() {
    int e = blockIdx.z;
    int segStart = g_offsets[e];
    int segLen = g_offsets[e + 1] - segStart;
    int row0 = blockIdx.y * 128;
    if (row0 >= segLen) return;
    int n0 = blockIdx.x * 64;

    extern __shared__ __align__(16) char smem[];
    uint32_t sb = smem_u32(smem);
    float* scr = (float*)smem;

    int tid = threadIdx.x, lane = tid & 31, wid = tid >> 5;
    int warp_m = wid & 3, warp_n = wid >> 2;

    int ar = tid >> 1;
    uint32_t aoff = (uint32_t)ar * 80 + (uint32_t)(tid & 1) * 32;
    int gr_a = row0 + ar;
    bool okA = gr_a < segLen;
    uint32_t an = okA ? 16u : 0u;
    const __half* aptr = g_xh + (size_t)(okA ? g_tok[segStart + gr_a] : 0) * DD
                       + (tid & 1) * 16;
    int br = tid >> 3;
    uint32_t boff = (uint32_t)br * 144 + (uint32_t)(tid & 7) * 16;
    const __half* b1ptr = g_w1h + ((size_t)e * DD + br) * HH + n0 + (tid & 7) * 8;
    const __half* b3ptr = g_w3h + ((size_t)e * DD + br) * HH + n0 + (tid & 7) * 8;

    wmma::fragment<wmma::accumulator, 16, 16, 16, float> acc1[2][2], acc3[2][2];
#pragma unroll
    for (int mt = 0; mt < 2; mt++)
#pragma unroll
        for (int nt = 0; nt < 2; nt++) {
            wmma::fill_fragment(acc1[mt][nt], 0.f);
            wmma::fill_fragment(acc3[mt][nt], 0.f);
        }

    const int NS = DD / 32;
    // prologue: issue stages 0..2
#pragma unroll
    for (int s = 0; s < 3; s++) {
        uint32_t st = sb + (uint32_t)s * STG1;
        int k0 = s * 32;
        cp16(st + aoff,         aptr + k0, an);
        cp16(st + aoff + 16,    aptr + k0 + 8, an);
        cp16(st + 10240 + boff, b1ptr + (size_t)k0 * HH, 16u);
        cp16(st + 14848 + boff, b3ptr + (size_t)k0 * HH, 16u);
        cp_commit();
    }

    for (int s = 0; s < NS; s++) {
        cp_wait<2>();        // stage s arrived
        __syncthreads();     // buffer (s+3)%4 == (s-1)%4 now provably free
        // issue next-stage loads BEFORE compute (extra latency cover)
        if (s + 3 < NS) {
            uint32_t st = sb + (uint32_t)((s + 3) & 3) * STG1;
            int k0 = (s + 3) * 32;
            cp16(st + aoff,         aptr + k0, an);
            cp16(st + aoff + 16,    aptr + k0 + 8, an);
            cp16(st + 10240 + boff, b1ptr + (size_t)k0 * HH, 16u);
            cp16(st + 14848 + boff, b3ptr + (size_t)k0 * HH, 16u);
        }
        cp_commit();         // lockstep group count (empty group on tail)
        const char* buf = smem + (size_t)(s & 3) * STG1;
        const __half* cA  = (const __half*)buf;
        const __half* cB1 = (const __half*)(buf + 10240);
        const __half* cB3 = (const __half*)(buf + 14848);
#pragma unroll
        for (int kt = 0; kt < 2; kt++) {
            wmma::fragment<wmma::matrix_a, 16, 16, 16, __half, wmma::row_major> af[2];
            wmma::load_matrix_sync(af[0], cA + (warp_m * 32) * 40 + kt * 16, 40);
            wmma::load_matrix_sync(af[1], cA + (warp_m * 32 + 16) * 40 + kt * 16, 40);
#pragma unroll
            for (int nt = 0; nt < 2; nt++) {
                wmma::fragment<wmma::matrix_b, 16, 16, 16, __half, wmma::row_major> bf;
                wmma::load_matrix_sync(bf, cB1 + (kt * 16) * 72 + warp_n * 32 + nt * 16, 72);
                wmma::mma_sync(acc1[0][nt], af[0], bf, acc1[0][nt]);
                wmma::mma_sync(acc1[1][nt], af[1], bf, acc1[1][nt]);
                wmma::load_matrix_sync(bf, cB3 + (kt * 16) * 72 + warp_n * 32 + nt * 16, 72);
                wmma::mma_sync(acc3[0][nt], af[0], bf, acc3[0][nt]);
                wmma::mma_sync(acc3[1][nt], af[1], bf, acc3[1][nt]);
            }
        }
    }
    cp_wait<0>();
    __syncthreads();

    // epilogue: silu * gate * weight -> fp16 h
    float* w = scr + wid * 512;
    int r = lane >> 1, c = (lane & 1) * 8;
#pragma unroll
    for (int mt = 0; mt < 2; mt++) {
#pragma unroll
        for (int nt = 0; nt < 2; nt++) {
            wmma::store_matrix_sync(w, acc1[mt][nt], 16, wmma::mem_row_major);
            wmma::store_matrix_sync(w + 256, acc3[mt][nt], 16, wmma::mem_row_major);
            __syncwarp();
            int gr = row0 + warp_m * 32 + mt * 16 + r;
            if (gr < segLen) {
                float wgt = g_wgt[segStart + gr];
                __half* hp = g_h + (size_t)(segStart + gr) * HH + n0 + warp_n * 32 + nt * 16 + c;
#pragma unroll
                for (int j = 0; j < 8; j += 2) {
                    float f0 = wgt * silu_f(w[r * 16 + c + j])     * w[256 + r * 16 + c + j];
                    float f1 = wgt * silu_f(w[r * 16 + c + j + 1]) * w[256 + r * 16 + c + j + 1];
                    *(__half2*)(hp + j) = __floats2half2_rn(f0, f1);
                }
            }
            __syncwarp();
        }
    }
}

// ============================================================================
// GEMM2: out[tok] += h @ w2 — wmma, 128M x 128N x 32K
// 4-stage cp.async pipeline; next-stage loads issued BEFORE compute.
// stage 18944B: sA(128x40h) @0, sB(32x136h) @10240
// ============================================================================
#define STG2 18944
#define SM2_BYTES (4 * STG2)   // 75776

__global__ void __launch_bounds__(256) k_gemm2(float* __restrict__ out) {
    int e = blockIdx.z;
    int segStart = g_offsets[e];
    int segLen = g_offsets[e + 1] - segStart;
    int row0 = blockIdx.y * 128;
    if (row0 >= segLen) return;
    int n0 = blockIdx.x * 128;

    extern __shared__ __align__(16) char smem[];
    uint32_t sb = smem_u32(smem);
    float* scr = (float*)smem;

    int tid = threadIdx.x, lane = tid & 31, wid = tid >> 5;
    int warp_m = wid & 3, warp_n = wid >> 2;

    int ar = tid >> 1;
    uint32_t aoff = (uint32_t)ar * 80 + (uint32_t)(tid & 1) * 32;
    int gr_a = row0 + ar;
    bool okA = gr_a < segLen;
    uint32_t an = okA ? 16u : 0u;
    const __half* aptr = g_h + (size_t)(segStart + (okA ? gr_a : 0)) * HH + (tid & 1) * 16;
    int br = tid >> 3;
    uint32_t boff = (uint32_t)br * 272 + (uint32_t)(tid & 7) * 32;
    const __half* bptr = g_w2h + ((size_t)e * HH + br) * DD + n0 + (tid & 7) * 16;

    wmma::fragment<wmma::accumulator, 16, 16, 16, float> acc[2][4];
#pragma unroll
    for (int mt = 0; mt < 2; mt++)
#pragma unroll
        for (int nt = 0; nt < 4; nt++) wmma::fill_fragment(acc[mt][nt], 0.f);

    const int NS = HH / 32;
#pragma unroll
    for (int s = 0; s < 3; s++) {
        uint32_t st = sb + (uint32_t)s * STG2;
        int k0 = s * 32;
        cp16(st + aoff,          aptr + k0, an);
        cp16(st + aoff + 16,     aptr + k0 + 8, an);
        cp16(st + 10240 + boff,      bptr + (size_t)k0 * DD, 16u);
        cp16(st + 10240 + boff + 16, bptr + (size_t)k0 * DD + 8, 16u);
        cp_commit();
    }

    for (int s = 0; s < NS; s++) {
        cp_wait<2>();
        __syncthreads();
        if (s + 3 < NS) {
            uint32_t st = sb + (uint32_t)((s + 3) & 3) * STG2;
            int k0 = (s + 3) * 32;
            cp16(st + aoff,          aptr + k0, an);
            cp16(st + aoff + 16,     aptr + k0 + 8, an);
            cp16(st + 10240 + boff,      bptr + (size_t)k0 * DD, 16u);
            cp16(st + 10240 + boff + 16, bptr + (size_t)k0 * DD + 8, 16u);
        }
        cp_commit();
        const char* buf = smem + (size_t)(s & 3) * STG2;
        const __half* cA = (const __half*)buf;
        const __half* cB = (const __half*)(buf + 10240);
#pragma unroll
        for (int kt = 0; kt < 2; kt++) {
            wmma::fragment<wmma::matrix_a, 16, 16, 16, __half, wmma::row_major> af[2];
            wmma::load_matrix_sync(af[0], cA + (warp_m * 32) * 40 + kt * 16, 40);
            wmma::load_matrix_sync(af[1], cA + (warp_m * 32 + 16) * 40 + kt * 16, 40);
#pragma unroll
            for (int nt = 0; nt < 4; nt++) {
                wmma::fragment<wmma::matrix_b, 16, 16, 16, __half, wmma::row_major> bf;
                wmma::load_matrix_sync(bf, cB + (kt * 16) * 136 + warp_n * 64 + nt * 16, 136);
                wmma::mma_sync(acc[0][nt], af[0], bf, acc[0][nt]);
                wmma::mma_sync(acc[1][nt], af[1], bf, acc[1][nt]);
            }
        }
    }
    cp_wait<0>();
    __syncthreads();

    // epilogue: atomicAdd into out
    float* w = scr + wid * 256;
    int r = lane >> 1, c = (lane & 1) * 8;
#pragma unroll
    for (int mt = 0; mt < 2; mt++) {
#pragma unroll
        for (int nt = 0; nt < 4; nt++) {
            wmma::store_matrix_sync(w, acc[mt][nt], 16, wmma::mem_row_major);
            __syncwarp();
            int gr = row0 + warp_m * 32 + mt * 16 + r;
            if (gr < segLen) {
                int tok = g_tok[segStart + gr];
                float* pp = out + (size_t)tok * DD + n0 + warp_n * 64 + nt * 16 + c;
#pragma unroll
                for (int j = 0; j < 8; j++) atomicAdd(pp + j, w[r * 16 + c + j]);
            }
            __syncwarp();
        }
    }
}

// ---------------- launch ----------------
extern "C" void kernel_launch(void* const* d_in, const int* in_sizes, int n_in,
                              void* d_out, int out_size) {
    const float* x  = (const float*)d_in[0];
    const float* gw = (const float*)d_in[1];
    const float* w1 = (const float*)d_in[2];
    const float* w3 = (const float*)d_in[3];
    const float* w2 = (const float*)d_in[4];
    float* out = (float*)d_out;

    cudaFuncSetAttribute(k_gemm1, cudaFuncAttributeMaxDynamicSharedMemorySize, SM1_BYTES);
    cudaFuncSetAttribute(k_gemm2, cudaFuncAttributeMaxDynamicSharedMemorySize, SM2_BYTES);

    k_init<<<4096, 256>>>(out);
    k_xtoh<<<TT * DD / 8 / 256, 256>>>(x);
    k_w1toh<<<EE * DD * HH / 8 / 256, 256>>>(w1);
    k_w3toh<<<EE * DD * HH / 8 / 256, 256>>>(w3);
    k_w2toh<<<EE * HH * DD / 8 / 256, 256>>>(w2);
    k_gate<<<TT / 8, 256>>>(x, gw);
    k_scan<<<1, 1>>>();
    k_scatter<<<TT / 256, 256>>>();
    k_gemm1<<<dim3(HH / 64, TT / 128, EE), 256, SM1_BYTES>>>();
    k_gemm2<<<dim3(DD / 128, TT / 128, EE), 256, SM2_BYTES>>>(out);
}

// round 17
// speedup vs baseline: 1.0889x; 1.0889x over previous
#include <cuda_runtime.h>
#include <cuda_fp16.h>
#include <mma.h>
#include <math.h>
#include <stdint.h>

using namespace nvcuda;

// ---------------- problem constants ----------------
#define TT 8192
#define DD 1024
#define EE 8
#define HH 3072
#define PP (TT * 2)

// ---------------- scratch (device globals; ~267 MB) ----------------
__device__ int    g_counts[EE];
__device__ int    g_cursor[EE];
__device__ int    g_offsets[EE + 1];
__device__ int    g_tok[PP];
__device__ float  g_wgt[PP];
__device__ int    g_te[TT * 2];
__device__ float  g_tw[TT * 2];
__device__ __half g_xh[(size_t)TT * DD];
__device__ __half g_w1h[(size_t)EE * DD * HH];
__device__ __half g_w3h[(size_t)EE * DD * HH];
__device__ __half g_w2h[(size_t)EE * HH * DD];
__device__ __half g_h[(size_t)PP * HH];

__device__ __forceinline__ float silu_f(float a) { return a / (1.f + __expf(-a)); }

__device__ __forceinline__ uint4 f8h8(float4 a, float4 b) {
    __half2 h0 = __floats2half2_rn(a.x, a.y);
    __half2 h1 = __floats2half2_rn(a.z, a.w);
    __half2 h2 = __floats2half2_rn(b.x, b.y);
    __half2 h3 = __floats2half2_rn(b.z, b.w);
    uint4 u;
    u.x = *(uint32_t*)&h0; u.y = *(uint32_t*)&h1;
    u.z = *(uint32_t*)&h2; u.w = *(uint32_t*)&h3;
    return u;
}
__device__ __forceinline__ uint32_t smem_u32(const void* p) {
    uint32_t a;
    asm("{ .reg .u64 t; cvta.to.shared.u64 t, %1; cvt.u32.u64 %0, t; }" : "=r"(a) : "l"(p));
    return a;
}
__device__ __forceinline__ void cp16(uint32_t dst, const void* src, uint32_t nbytes) {
    asm volatile("cp.async.cg.shared.global [%0], [%1], 16, %2;"
                 :: "r"(dst), "l"(src), "r"(nbytes));
}
__device__ __forceinline__ void cp_commit() { asm volatile("cp.async.commit_group;"); }
template <int N>
__device__ __forceinline__ void cp_wait() { asm volatile("cp.async.wait_group %0;" :: "n"(N)); }

// ---------------- init ----------------
__global__ void k_init(float* __restrict__ out) {
    int i = blockIdx.x * blockDim.x + threadIdx.x;
    if (i < EE) { g_counts[i] = 0; g_cursor[i] = 0; }
    int stride = gridDim.x * blockDim.x;
    for (int j = i; j < TT * DD; j += stride) out[j] = 0.f;
}

// ---- single fused conversion kernel: x, w1, w3, w2 -> fp16 (device symbols
// referenced DIRECTLY; sources are harness pointers passed as args) ----
#define NX_CH  (TT * DD / 8)            // x chunks (uint4 of 8 halves)
#define NW_CH  (EE * DD * HH / 8)       // per-weight chunks
__global__ void k_convert_all(const float* __restrict__ x,
                              const float* __restrict__ w1,
                              const float* __restrict__ w3,
                              const float* __restrict__ w2) {
    size_t c = (size_t)blockIdx.x * blockDim.x + threadIdx.x;
    const float* src;
    __half* dst;
    size_t off;
    if (c < NX_CH)                { src = x;  dst = g_xh;  off = c; }
    else if (c < NX_CH + NW_CH)   { src = w1; dst = g_w1h; off = c - NX_CH; }
    else if (c < NX_CH + 2*NW_CH) { src = w3; dst = g_w3h; off = c - NX_CH - NW_CH; }
    else                          { src = w2; dst = g_w2h; off = c - NX_CH - 2*NW_CH; }
    size_t i = off * 8;
    float4 a = *(const float4*)(src + i);
    float4 b = *(const float4*)(src + i + 4);
    *(uint4*)(dst + i) = f8h8(a, b);
}

// ---------------- gating (R13 form) ----------------
__global__ void k_gate(const float* __restrict__ x, const float* __restrict__ gw) {
    int gid = blockIdx.x * blockDim.x + threadIdx.x;
    int t = gid >> 5, lane = gid & 31;
    if (t >= TT) return;
    const float* xr = x + (size_t)t * DD;
    float acc[EE];
#pragma unroll
    for (int e = 0; e < EE; e++) acc[e] = 0.f;
    for (int d = lane; d < DD; d += 32) {
        float xv = xr[d];
        const float4* g4 = (const float4*)(gw + (size_t)d * EE);
        float4 a = g4[0], b = g4[1];
        acc[0] += xv * a.x; acc[1] += xv * a.y; acc[2] += xv * a.z; acc[3] += xv * a.w;
        acc[4] += xv * b.x; acc[5] += xv * b.y; acc[6] += xv * b.z; acc[7] += xv * b.w;
    }
#pragma unroll
    for (int e = 0; e < EE; e++)
#pragma unroll
        for (int o = 16; o; o >>= 1) acc[e] += __shfl_xor_sync(0xffffffffu, acc[e], o);
    if (lane == 0) {
        int e0 = 0;
#pragma unroll
        for (int e = 1; e < EE; e++) if (acc[e] > acc[e0]) e0 = e;
        int e1 = (e0 == 0) ? 1 : 0;
#pragma unroll
        for (int e = 0; e < EE; e++) if (e != e0 && acc[e] > acc[e1]) e1 = e;
        float w0 = 1.f / (1.f + expf(acc[e1] - acc[e0]));
        g_te[2 * t] = e0; g_te[2 * t + 1] = e1;
        g_tw[2 * t] = w0; g_tw[2 * t + 1] = 1.f - w0;
        atomicAdd(&g_counts[e0], 1);
        atomicAdd(&g_counts[e1], 1);
    }
}

__global__ void k_scan() {
    int s = 0;
    g_offsets[0] = 0;
    for (int e = 0; e < EE; e++) { s += g_counts[e]; g_offsets[e + 1] = s; }
}

__global__ void k_scatter() {
    int t = blockIdx.x * blockDim.x + threadIdx.x;
    if (t >= TT) return;
#pragma unroll
    for (int k = 0; k < 2; k++) {
        int e = g_te[2 * t + k];
        int pos = g_offsets[e] + atomicAdd(&g_cursor[e], 1);
        g_tok[pos] = t;
        g_wgt[pos] = g_tw[2 * t + k];
    }
}

// ============================================================================
// GEMM1 (R13 EXACT): wmma, 128M x 64N x 32K, 4-stage cp.async,
// one __syncthreads per stage, loads issued AFTER compute.
// stage 19456B: sA(128x40h) @0, sB1(32x72h) @10240, sB3 @14848
// ============================================================================
#define STG1 19456
#define SM1_BYTES (4 * STG1)   // 77824

__global__ void __launch_bounds__(256) k_gemm1() {
    int e = blockIdx.z;
    int segStart = g_offsets[e];
    int segLen = g_offsets[e + 1] - segStart;
    int row0 = blockIdx.y * 128;
    if (row0 >= segLen) return;
    int n0 = blockIdx.x * 64;

    extern __shared__ __align__(16) char smem[];
    uint32_t sb = smem_u32(smem);
    float* scr = (float*)smem;

    int tid = threadIdx.x, lane = tid & 31, wid = tid >> 5;
    int warp_m = wid & 3, warp_n = wid >> 2;

    int ar = tid >> 1;
    uint32_t aoff = (uint32_t)ar * 80 + (uint32_t)(tid & 1) * 32;
    int gr_a = row0 + ar;
    bool okA = gr_a < segLen;
    uint32_t an = okA ? 16u : 0u;
    const __half* aptr = g_xh + (size_t)(okA ? g_tok[segStart + gr_a] : 0) * DD
                       + (tid & 1) * 16;
    int br = tid >> 3;
    uint32_t boff = (uint32_t)br * 144 + (uint32_t)(tid & 7) * 16;
    const __half* b1ptr = g_w1h + ((size_t)e * DD + br) * HH + n0 + (tid & 7) * 8;
    const __half* b3ptr = g_w3h + ((size_t)e * DD + br) * HH + n0 + (tid & 7) * 8;

    wmma::fragment<wmma::accumulator, 16, 16, 16, float> acc1[2][2], acc3[2][2];
#pragma unroll
    for (int mt = 0; mt < 2; mt++)
#pragma unroll
        for (int nt = 0; nt < 2; nt++) {
            wmma::fill_fragment(acc1[mt][nt], 0.f);
            wmma::fill_fragment(acc3[mt][nt], 0.f);
        }

    const int NS = DD / 32;
#pragma unroll
    for (int s = 0; s < 3; s++) {
        uint32_t st = sb + (uint32_t)s * STG1;
        int k0 = s * 32;
        cp16(st + aoff,         aptr + k0, an);
        cp16(st + aoff + 16,    aptr + k0 + 8, an);
        cp16(st + 10240 + boff, b1ptr + (size_t)k0 * HH, 16u);
        cp16(st + 14848 + boff, b3ptr + (size_t)k0 * HH, 16u);
        cp_commit();
    }

    for (int s = 0; s < NS; s++) {
        cp_wait<2>();
        __syncthreads();
        const char* buf = smem + (size_t)(s & 3) * STG1;
        const __half* cA  = (const __half*)buf;
        const __half* cB1 = (const __half*)(buf + 10240);
        const __half* cB3 = (const __half*)(buf + 14848);
#pragma unroll
        for (int kt = 0; kt < 2; kt++) {
            wmma::fragment<wmma::matrix_a, 16, 16, 16, __half, wmma::row_major> af[2];
            wmma::load_matrix_sync(af[0], cA + (warp_m * 32) * 40 + kt * 16, 40);
            wmma::load_matrix_sync(af[1], cA + (warp_m * 32 + 16) * 40 + kt * 16, 40);
#pragma unroll
            for (int nt = 0; nt < 2; nt++) {
                wmma::fragment<wmma::matrix_b, 16, 16, 16, __half, wmma::row_major> bf;
                wmma::load_matrix_sync(bf, cB1 + (kt * 16) * 72 + warp_n * 32 + nt * 16, 72);
                wmma::mma_sync(acc1[0][nt], af[0], bf, acc1[0][nt]);
                wmma::mma_sync(acc1[1][nt], af[1], bf, acc1[1][nt]);
                wmma::load_matrix_sync(bf, cB3 + (kt * 16) * 72 + warp_n * 32 + nt * 16, 72);
                wmma::mma_sync(acc3[0][nt], af[0], bf, acc3[0][nt]);
                wmma::mma_sync(acc3[1][nt], af[1], bf, acc3[1][nt]);
            }
        }
        if (s + 3 < NS) {
            uint32_t st = sb + (uint32_t)((s + 3) & 3) * STG1;
            int k0 = (s + 3) * 32;
            cp16(st + aoff,         aptr + k0, an);
            cp16(st + aoff + 16,    aptr + k0 + 8, an);
            cp16(st + 10240 + boff, b1ptr + (size_t)k0 * HH, 16u);
            cp16(st + 14848 + boff, b3ptr + (size_t)k0 * HH, 16u);
        }
        cp_commit();
    }
    cp_wait<0>();
    __syncthreads();

    float* w = scr + wid * 512;
    int r = lane >> 1, c = (lane & 1) * 8;
#pragma unroll
    for (int mt = 0; mt < 2; mt++) {
#pragma unroll
        for (int nt = 0; nt < 2; nt++) {
            wmma::store_matrix_sync(w, acc1[mt][nt], 16, wmma::mem_row_major);
            wmma::store_matrix_sync(w + 256, acc3[mt][nt], 16, wmma::mem_row_major);
            __syncwarp();
            int gr = row0 + warp_m * 32 + mt * 16 + r;
            if (gr < segLen) {
                float wgt = g_wgt[segStart + gr];
                __half* hp = g_h + (size_t)(segStart + gr) * HH + n0 + warp_n * 32 + nt * 16 + c;
#pragma unroll
                for (int j = 0; j < 8; j += 2) {
                    float f0 = wgt * silu_f(w[r * 16 + c + j])     * w[256 + r * 16 + c + j];
                    float f1 = wgt * silu_f(w[r * 16 + c + j + 1]) * w[256 + r * 16 + c + j + 1];
                    *(__half2*)(hp + j) = __floats2half2_rn(f0, f1);
                }
            }
            __syncwarp();
        }
    }
}

// ============================================================================
// GEMM2 (R13 EXACT): wmma, 128M x 128N x 32K, 4-stage cp.async,
// one __syncthreads per stage, loads issued AFTER compute.
// stage 18944B: sA(128x40h) @0, sB(32x136h) @10240
// ============================================================================
#define STG2 18944
#define SM2_BYTES (4 * STG2)   // 75776

__global__ void __launch_bounds__(256) k_gemm2(float* __restrict__ out) {
    int e = blockIdx.z;
    int segStart = g_offsets[e];
    int segLen = g_offsets[e + 1] - segStart;
    int row0 = blockIdx.y * 128;
    if (row0 >= segLen) return;
    int n0 = blockIdx.x * 128;

    extern __shared__ __align__(16) char smem[];
    uint32_t sb = smem_u32(smem);
    float* scr = (float*)smem;

    int tid = threadIdx.x, lane = tid & 31, wid = tid >> 5;
    int warp_m = wid & 3, warp_n = wid >> 2;

    int ar = tid >> 1;
    uint32_t aoff = (uint32_t)ar * 80 + (uint32_t)(tid & 1) * 32;
    int gr_a = row0 + ar;
    bool okA = gr_a < segLen;
    uint32_t an = okA ? 16u : 0u;
    const __half* aptr = g_h + (size_t)(segStart + (okA ? gr_a : 0)) * HH + (tid & 1) * 16;
    int br = tid >> 3;
    uint32_t boff = (uint32_t)br * 272 + (uint32_t)(tid & 7) * 32;
    const __half* bptr = g_w2h + ((size_t)e * HH + br) * DD + n0 + (tid & 7) * 16;

    wmma::fragment<wmma::accumulator, 16, 16, 16, float> acc[2][4];
#pragma unroll
    for (int mt = 0; mt < 2; mt++)
#pragma unroll
        for (int nt = 0; nt < 4; nt++) wmma::fill_fragment(acc[mt][nt], 0.f);

    const int NS = HH / 32;
#pragma unroll
    for (int s = 0; s < 3; s++) {
        uint32_t st = sb + (uint32_t)s * STG2;
        int k0 = s * 32;
        cp16(st + aoff,          aptr + k0, an);
        cp16(st + aoff + 16,     aptr + k0 + 8, an);
        cp16(st + 10240 + boff,      bptr + (size_t)k0 * DD, 16u);
        cp16(st + 10240 + boff + 16, bptr + (size_t)k0 * DD + 8, 16u);
        cp_commit();
    }

    for (int s = 0; s < NS; s++) {
        cp_wait<2>();
        __syncthreads();
        const char* buf = smem + (size_t)(s & 3) * STG2;
        const __half* cA = (const __half*)buf;
        const __half* cB = (const __half*)(buf + 10240);
#pragma unroll
        for (int kt = 0; kt < 2; kt++) {
            wmma::fragment<wmma::matrix_a, 16, 16, 16, __half, wmma::row_major> af[2];
            wmma::load_matrix_sync(af[0], cA + (warp_m * 32) * 40 + kt * 16, 40);
            wmma::load_matrix_sync(af[1], cA + (warp_m * 32 + 16) * 40 + kt * 16, 40);
#pragma unroll
            for (int nt = 0; nt < 4; nt++) {
                wmma::fragment<wmma::matrix_b, 16, 16, 16, __half, wmma::row_major> bf;
                wmma::load_matrix_sync(bf, cB + (kt * 16) * 136 + warp_n * 64 + nt * 16, 136);
                wmma::mma_sync(acc[0][nt], af[0], bf, acc[0][nt]);
                wmma::mma_sync(acc[1][nt], af[1], bf, acc[1][nt]);
            }
        }
        if (s + 3 < NS) {
            uint32_t st = sb + (uint32_t)((s + 3) & 3) * STG2;
            int k0 = (s + 3) * 32;
            cp16(st + aoff,          aptr + k0, an);
            cp16(st + aoff + 16,     aptr + k0 + 8, an);
            cp16(st + 10240 + boff,      bptr + (size_t)k0 * DD, 16u);
            cp16(st + 10240 + boff + 16, bptr + (size_t)k0 * DD + 8, 16u);
        }
        cp_commit();
    }
    cp_wait<0>();
    __syncthreads();

    float* w = scr + wid * 256;
    int r = lane >> 1, c = (lane & 1) * 8;
#pragma unroll
    for (int mt = 0; mt < 2; mt++) {
#pragma unroll
        for (int nt = 0; nt < 4; nt++) {
            wmma::store_matrix_sync(w, acc[mt][nt], 16, wmma::mem_row_major);
            __syncwarp();
            int gr = row0 + warp_m * 32 + mt * 16 + r;
            if (gr < segLen) {
                int tok = g_tok[segStart + gr];
                float* pp = out + (size_t)tok * DD + n0 + warp_n * 64 + nt * 16 + c;
#pragma unroll
                for (int j = 0; j < 8; j++) atomicAdd(pp + j, w[r * 16 + c + j]);
            }
            __syncwarp();
        }
    }
}

// ---------------- launch ----------------
extern "C" void kernel_launch(void* const* d_in, const int* in_sizes, int n_in,
                              void* d_out, int out_size) {
    const float* x  = (const float*)d_in[0];
    const float* gw = (const float*)d_in[1];
    const float* w1 = (const float*)d_in[2];
    const float* w3 = (const float*)d_in[3];
    const float* w2 = (const float*)d_in[4];
    float* out = (float*)d_out;

    cudaFuncSetAttribute(k_gemm1, cudaFuncAttributeMaxDynamicSharedMemorySize, SM1_BYTES);
    cudaFuncSetAttribute(k_gemm2, cudaFuncAttributeMaxDynamicSharedMemorySize, SM2_BYTES);

    k_init<<<4096, 256>>>(out);
    k_convert_all<<<(NX_CH + 3 * NW_CH) / 256, 256>>>(x, w1, w3, w2);
    k_gate<<<TT / 8, 256>>>(x, gw);
    k_scan<<<1, 1>>>();
    k_scatter<<<TT / 256, 256>>>();
    k_gemm1<<<dim3(HH / 64, TT / 128, EE), 256, SM1_BYTES>>>();
    k_gemm2<<<dim3(DD / 128, TT / 128, EE), 256, SM2_BYTES>>>(out);
}